// round 2
// baseline (speedup 1.0000x reference)
#include <cuda_runtime.h>
#include <math.h>

#define T_MAX 9792
#define EMB 1024
#define NH 16
#define DH 64

// ---------------- scratch (device globals; no allocs allowed) ----------------
__device__ float g_q[(size_t)T_MAX * EMB];
__device__ float g_k[(size_t)T_MAX * EMB];
__device__ float g_v[(size_t)T_MAX * EMB];
__device__ float g_attn[(size_t)T_MAX * EMB];
__device__ int   g_cu[64];

// ---------------- cumulative sequence lengths ----------------
__global__ void cu_seqlen_kernel(const int* __restrict__ seq_len, int B) {
    if (threadIdx.x == 0 && blockIdx.x == 0) {
        int s = 0;
        g_cu[0] = 0;
        for (int b = 0; b < B; b++) { s += seq_len[b]; g_cu[b + 1] = s; }
    }
}

// ---------------- SGEMM: C[M,N] = A[M,K] @ W[N,K]^T + bias ----------------
#define BM 128
#define BN 128
#define BK 16

__global__ __launch_bounds__(256) void sgemm_nt_bias(
    const float* __restrict__ A, const float* __restrict__ W,
    const float* __restrict__ bias, float* __restrict__ C, int M)
{
    __shared__ float As[BK][BM + 1];
    __shared__ float Bs[BK][BN + 1];
    const int N = EMB, K = EMB;
    const int row0 = blockIdx.y * BM;
    const int col0 = blockIdx.x * BN;
    const int tid = threadIdx.x;
    const int tx = tid & 15, ty = tid >> 4;
    const int lk = (tid & 3) * 4;   // k offset within tile (float4)
    const int lr = tid >> 2;        // row within 64

    float acc[8][8];
    #pragma unroll
    for (int i = 0; i < 8; i++)
        #pragma unroll
        for (int j = 0; j < 8; j++) acc[i][j] = 0.f;

    for (int k0 = 0; k0 < K; k0 += BK) {
        #pragma unroll
        for (int i = 0; i < 2; i++) {
            int r = lr + i * 64;
            int ar = row0 + r;
            float4 va = make_float4(0.f, 0.f, 0.f, 0.f);
            if (ar < M) va = *(const float4*)(A + (size_t)ar * K + k0 + lk);
            As[lk + 0][r] = va.x; As[lk + 1][r] = va.y;
            As[lk + 2][r] = va.z; As[lk + 3][r] = va.w;
            float4 vb = *(const float4*)(W + (size_t)(col0 + r) * K + k0 + lk);
            Bs[lk + 0][r] = vb.x; Bs[lk + 1][r] = vb.y;
            Bs[lk + 2][r] = vb.z; Bs[lk + 3][r] = vb.w;
        }
        __syncthreads();
        #pragma unroll
        for (int k = 0; k < BK; k++) {
            float a[8], b[8];
            #pragma unroll
            for (int i = 0; i < 8; i++) a[i] = As[k][ty * 8 + i];
            #pragma unroll
            for (int j = 0; j < 8; j++) b[j] = Bs[k][tx * 8 + j];
            #pragma unroll
            for (int i = 0; i < 8; i++)
                #pragma unroll
                for (int j = 0; j < 8; j++) acc[i][j] += a[i] * b[j];
        }
        __syncthreads();
    }

    #pragma unroll
    for (int i = 0; i < 8; i++) {
        int r = row0 + ty * 8 + i;
        if (r >= M) continue;
        #pragma unroll
        for (int j = 0; j < 8; j++) {
            int c = col0 + tx * 8 + j;
            float v = acc[i][j] + (bias ? bias[c] : 0.f);
            C[(size_t)r * N + c] = v;
        }
    }
}

// ---------------- RoPE (in place on g_q, g_k) ----------------
__global__ void rope_kernel(const float* __restrict__ cosb,
                            const float* __restrict__ sinb, int T)
{
    int idx = blockIdx.x * blockDim.x + threadIdx.x;
    int total = T * NH * 32;
    if (idx >= total) return;
    int i = idx & 31;
    int h = (idx >> 5) & 15;
    int t = idx >> 9;
    float c = cosb[t * DH + i];
    float s = sinb[t * DH + i];
    size_t base = (size_t)t * EMB + h * DH;
    float q0 = g_q[base + i], q1 = g_q[base + i + 32];
    g_q[base + i]      = q0 * c - q1 * s;
    g_q[base + i + 32] = q1 * c + q0 * s;
    float k0 = g_k[base + i], k1 = g_k[base + i + 32];
    g_k[base + i]      = k0 * c - k1 * s;
    g_k[base + i + 32] = k1 * c + k0 * s;
}

// ---------------- varlen causal flash attention ----------------
#define AQ 128   // query rows per block (== blockDim.x)
#define AK 64    // key tile
#define QPAD 68  // padded Q row stride (floats) to avoid bank conflicts

__global__ __launch_bounds__(128) void attn_kernel()
{
    extern __shared__ float sm[];
    float* Qs = sm;                  // AQ * QPAD
    float* Ks = sm + AQ * QPAD;      // AK * DH
    float* Vs = Ks + AK * DH;        // AK * DH

    const int b = blockIdx.z, h = blockIdx.y, qt = blockIdx.x;
    const int s0 = g_cu[b];
    const int L = g_cu[b + 1] - s0;
    const int q0 = qt * AQ;
    if (q0 >= L) return;
    const int tid = threadIdx.x;

    // load Q tile (coalesced)
    #pragma unroll
    for (int it = 0; it < 16; it++) {
        int f4 = it * 128 + tid;
        int r = f4 >> 4, c4 = f4 & 15;
        float4 v = make_float4(0.f, 0.f, 0.f, 0.f);
        if (q0 + r < L)
            v = *(const float4*)(g_q + (size_t)(s0 + q0 + r) * EMB + h * DH + c4 * 4);
        *(float4*)(Qs + r * QPAD + c4 * 4) = v;
    }

    const int grow = q0 + tid;
    const bool qv = grow < L;
    float m = -1e30f, l = 0.f;
    float acc[DH];
    #pragma unroll
    for (int d = 0; d < DH; d++) acc[d] = 0.f;

    const int kend = min(q0 + AQ, L);
    const int nkt = (kend + AK - 1) / AK;

    for (int kt = 0; kt < nkt; kt++) {
        __syncthreads();
        #pragma unroll
        for (int it = 0; it < 8; it++) {
            int f4 = it * 128 + tid;
            int r = f4 >> 4, c4 = f4 & 15;
            int krow = kt * AK + r;
            float4 kv = make_float4(0.f, 0.f, 0.f, 0.f);
            float4 vv = make_float4(0.f, 0.f, 0.f, 0.f);
            if (krow < L) {
                kv = *(const float4*)(g_k + (size_t)(s0 + krow) * EMB + h * DH + c4 * 4);
                vv = *(const float4*)(g_v + (size_t)(s0 + krow) * EMB + h * DH + c4 * 4);
            }
            *(float4*)(Ks + r * DH + c4 * 4) = kv;
            *(float4*)(Vs + r * DH + c4 * 4) = vv;
        }
        __syncthreads();

        if (!qv || kt * AK > grow) continue;

        float s[AK];
        #pragma unroll
        for (int j = 0; j < AK; j++) s[j] = 0.f;

        #pragma unroll
        for (int d0 = 0; d0 < DH; d0 += 16) {
            float4 q4[4];
            #pragma unroll
            for (int t4 = 0; t4 < 4; t4++)
                q4[t4] = *(const float4*)(Qs + tid * QPAD + d0 + t4 * 4);
            #pragma unroll
            for (int j = 0; j < AK; j++) {
                float sum = 0.f;
                #pragma unroll
                for (int t4 = 0; t4 < 4; t4++) {
                    float4 k4 = *(const float4*)(Ks + j * DH + d0 + t4 * 4);
                    sum += q4[t4].x * k4.x + q4[t4].y * k4.y
                         + q4[t4].z * k4.z + q4[t4].w * k4.w;
                }
                s[j] += sum;
            }
        }

        const float scale = 0.125f; // 1/sqrt(64)
        float mt = m;
        #pragma unroll
        for (int j = 0; j < AK; j++) {
            int jg = kt * AK + j;
            float sv = s[j] * scale;
            if (jg > grow || jg >= L) sv = -1e30f;
            s[j] = sv;
            mt = fmaxf(mt, sv);
        }
        float corr = __expf(m - mt);
        m = mt;
        l *= corr;
        #pragma unroll
        for (int d = 0; d < DH; d++) acc[d] *= corr;

        #pragma unroll
        for (int j = 0; j < AK; j++) {
            float p = __expf(s[j] - m);
            l += p;
            #pragma unroll
            for (int d4 = 0; d4 < 16; d4++) {
                float4 v4 = *(const float4*)(Vs + j * DH + d4 * 4);
                acc[d4 * 4 + 0] += p * v4.x;
                acc[d4 * 4 + 1] += p * v4.y;
                acc[d4 * 4 + 2] += p * v4.z;
                acc[d4 * 4 + 3] += p * v4.w;
            }
        }
    }

    if (qv) {
        float inv = 1.f / l;
        #pragma unroll
        for (int d4 = 0; d4 < 16; d4++) {
            float4 o;
            o.x = acc[d4 * 4 + 0] * inv;
            o.y = acc[d4 * 4 + 1] * inv;
            o.z = acc[d4 * 4 + 2] * inv;
            o.w = acc[d4 * 4 + 3] * inv;
            *(float4*)(g_attn + (size_t)(s0 + grow) * EMB + h * DH + d4 * 4) = o;
        }
    }
}

// ---------------- launch ----------------
extern "C" void kernel_launch(void* const* d_in, const int* in_sizes, int n_in,
                              void* d_out, int out_size)
{
    const float* hidden = (const float*)d_in[0];
    const float* cosb   = (const float*)d_in[1];
    const float* sinb   = (const float*)d_in[2];
    const float* q_w    = (const float*)d_in[3];
    const float* q_b    = (const float*)d_in[4];
    const float* k_w    = (const float*)d_in[5];
    const float* v_w    = (const float*)d_in[6];
    const float* v_b    = (const float*)d_in[7];
    const float* out_w  = (const float*)d_in[8];
    const float* out_b  = (const float*)d_in[9];
    const int*   seqlen = (const int*)d_in[10];
    float* out = (float*)d_out;

    const int T = in_sizes[0] / EMB;
    const int B = in_sizes[10];

    float *dq, *dk, *dv, *dattn;
    cudaGetSymbolAddress((void**)&dq, g_q);
    cudaGetSymbolAddress((void**)&dk, g_k);
    cudaGetSymbolAddress((void**)&dv, g_v);
    cudaGetSymbolAddress((void**)&dattn, g_attn);

    cu_seqlen_kernel<<<1, 32>>>(seqlen, B);

    dim3 gg(EMB / BN, (T + BM - 1) / BM);
    sgemm_nt_bias<<<gg, 256>>>(hidden, q_w, q_b, dq, T);
    sgemm_nt_bias<<<gg, 256>>>(hidden, k_w, nullptr, dk, T);
    sgemm_nt_bias<<<gg, 256>>>(hidden, v_w, v_b, dv, T);

    int rope_total = T * NH * 32;
    rope_kernel<<<(rope_total + 255) / 256, 256>>>(cosb, sinb, T);

    int smem = (AQ * QPAD + 2 * AK * DH) * sizeof(float);
    cudaFuncSetAttribute(attn_kernel, cudaFuncAttributeMaxDynamicSharedMemorySize, smem);
    dim3 ga(1024 / AQ, NH, B);
    attn_kernel<<<ga, 128, smem>>>();

    sgemm_nt_bias<<<gg, 256>>>(dattn, out_w, out_b, out, T);
}

// round 6
// speedup vs baseline: 1.6199x; 1.6199x over previous
#include <cuda_runtime.h>
#include <cuda_bf16.h>
#include <math.h>
#include <stdint.h>

#define T_MAX 9792
#define EMB 1024
#define NH 16
#define DH 64

// ---------------- scratch (device globals; no allocs allowed) ----------------
__device__ float g_q[(size_t)T_MAX * EMB];
__device__ float g_k[(size_t)T_MAX * EMB];
__device__ float g_v[(size_t)T_MAX * EMB];
__device__ float g_attn[(size_t)T_MAX * EMB];
__device__ int   g_cu[64];

// bf16 split buffers
__device__ __nv_bfloat16 g_hid_hi[(size_t)T_MAX * EMB];
__device__ __nv_bfloat16 g_hid_lo[(size_t)T_MAX * EMB];
__device__ __nv_bfloat16 g_w_hi[(size_t)4 * EMB * EMB];
__device__ __nv_bfloat16 g_w_lo[(size_t)4 * EMB * EMB];
__device__ __nv_bfloat16 g_at_hi[(size_t)T_MAX * EMB];
__device__ __nv_bfloat16 g_at_lo[(size_t)T_MAX * EMB];

// ---------------- PTX helpers ----------------
__device__ __forceinline__ uint32_t smem_u32(const void* p) {
    uint32_t a;
    asm("{ .reg .u64 t; cvta.to.shared.u64 t, %1; cvt.u32.u64 %0, t; }" : "=r"(a) : "l"(p));
    return a;
}

#define CPA(dst, src) \
    asm volatile("cp.async.cg.shared.global [%0], [%1], 16;" :: "r"(dst), "l"(src) : "memory")
#define CPA_COMMIT() asm volatile("cp.async.commit_group;" ::: "memory")

#define LDSM4(r, addr) \
    asm volatile("ldmatrix.sync.aligned.m8n8.x4.shared.b16 {%0,%1,%2,%3}, [%4];" \
        : "=r"((r)[0]), "=r"((r)[1]), "=r"((r)[2]), "=r"((r)[3]) : "r"(addr))

#define MMA(c, a, b0, b1) \
    asm volatile("mma.sync.aligned.m16n8k16.row.col.f32.bf16.bf16.f32 " \
        "{%0,%1,%2,%3}, {%4,%5,%6,%7}, {%8,%9}, {%0,%1,%2,%3};" \
        : "+f"((c)[0]), "+f"((c)[1]), "+f"((c)[2]), "+f"((c)[3]) \
        : "r"((a)[0]), "r"((a)[1]), "r"((a)[2]), "r"((a)[3]), "r"(b0), "r"(b1))

// ---------------- cumulative sequence lengths ----------------
__global__ void cu_seqlen_kernel(const int* __restrict__ seq_len, int B) {
    if (threadIdx.x == 0 && blockIdx.x == 0) {
        int s = 0;
        g_cu[0] = 0;
        for (int b = 0; b < B; b++) { s += seq_len[b]; g_cu[b + 1] = s; }
    }
}

// ---------------- fp32 -> (bf16 hi, bf16 lo) split ----------------
__global__ void cvt_split4(const float* __restrict__ x,
                           __nv_bfloat16* __restrict__ hi,
                           __nv_bfloat16* __restrict__ lo, int n4)
{
    int i = blockIdx.x * blockDim.x + threadIdx.x;
    if (i >= n4) return;
    float4 v = ((const float4*)x)[i];
    __nv_bfloat16 h0 = __float2bfloat16(v.x);
    __nv_bfloat16 h1 = __float2bfloat16(v.y);
    __nv_bfloat16 h2 = __float2bfloat16(v.z);
    __nv_bfloat16 h3 = __float2bfloat16(v.w);
    __nv_bfloat16 l0 = __float2bfloat16(v.x - __bfloat162float(h0));
    __nv_bfloat16 l1 = __float2bfloat16(v.y - __bfloat162float(h1));
    __nv_bfloat16 l2 = __float2bfloat16(v.z - __bfloat162float(h2));
    __nv_bfloat16 l3 = __float2bfloat16(v.w - __bfloat162float(h3));
    __nv_bfloat162* hp = (__nv_bfloat162*)hi;
    __nv_bfloat162* lp = (__nv_bfloat162*)lo;
    hp[2 * i]     = __halves2bfloat162(h0, h1);
    hp[2 * i + 1] = __halves2bfloat162(h2, h3);
    lp[2 * i]     = __halves2bfloat162(l0, l1);
    lp[2 * i + 1] = __halves2bfloat162(l2, l3);
}

// ---------------- mma.sync GEMM: C[M,1024] = A @ W^T + bias ----------------
// 3-product bf16 emulation per fragment: Ahi*Bhi + Ahi*Blo + Alo*Bhi (fp32 acc).
// Tiles: 128x128x32, 8 warps (2x4), warp tile 64x32, cp.async double buffer.
#define GBK 32
#define GNK (EMB / GBK)          // 32 k-chunks
#define LDB 80                   // padded row stride in bytes (40 bf16)
#define TILE_B (128 * LDB)       // 10240 bytes per tile
#define STG_B (4 * TILE_B)       // 40960 bytes per stage (AH, AL, BH, BL)
#define GEMM_SMEM (2 * STG_B)    // 81920

__global__ __launch_bounds__(256, 1)
void gemm_mma(const __nv_bfloat16* __restrict__ Ahi, const __nv_bfloat16* __restrict__ Alo,
              const __nv_bfloat16* __restrict__ Whi, const __nv_bfloat16* __restrict__ Wlo,
              const float* __restrict__ bias, float* __restrict__ C, int M)
{
    extern __shared__ char smem[];
    const uint32_t sbase = smem_u32(smem);
    const int tid = threadIdx.x;
    const int wid = tid >> 5, lane = tid & 31;
    const int row0 = blockIdx.y * 128, col0 = blockIdx.x * 128;
    const int wm = (wid >> 2) * 64, wn = (wid & 3) * 32;

    float acc[4][4][4];
    #pragma unroll
    for (int i = 0; i < 4; i++)
        #pragma unroll
        for (int j = 0; j < 4; j++)
            #pragma unroll
            for (int k = 0; k < 4; k++) acc[i][j][k] = 0.f;

    // per-thread load coords (2 x 16B per tile per thread)
    const int r_ld[2]  = { tid >> 2, (tid + 256) >> 2 };
    const int cb_ld    = (tid & 3) * 16;   // byte col in smem row
    const int ce_ld    = (tid & 3) * 8;    // bf16 elem col in gmem row

    auto LOAD = [&](int s, int k0) {
        #pragma unroll
        for (int h = 0; h < 2; h++) {
            int r = r_ld[h];
            uint32_t d = sbase + s * STG_B + r * LDB + cb_ld;
            int ga = min(row0 + r, M - 1);
            int gb = col0 + r;
            CPA(d,              Ahi + (size_t)ga * EMB + k0 + ce_ld);
            CPA(d + TILE_B,     Alo + (size_t)ga * EMB + k0 + ce_ld);
            CPA(d + 2 * TILE_B, Whi + (size_t)gb * EMB + k0 + ce_ld);
            CPA(d + 3 * TILE_B, Wlo + (size_t)gb * EMB + k0 + ce_ld);
        }
        CPA_COMMIT();
    };

    // fragment addresses (fixed per thread, vary by stage/ks)
    const uint32_t a_off = (uint32_t)((wm + (lane & 15)) * LDB + (lane >> 4) * 16);
    const uint32_t b_off = (uint32_t)(2 * TILE_B +
                         (wn + ((lane >> 4) << 3) + (lane & 7)) * LDB + ((lane >> 3) & 1) * 16);

    auto COMPUTE = [&](int s) {
        const uint32_t st = sbase + s * STG_B;
        #pragma unroll
        for (int ks = 0; ks < 2; ks++) {
            uint32_t ah[4][4], al[4][4];
            #pragma unroll
            for (int mf = 0; mf < 4; mf++) {
                uint32_t ra = st + a_off + mf * (16 * LDB) + ks * 32;
                LDSM4(ah[mf], ra);
                LDSM4(al[mf], ra + TILE_B);
            }
            uint32_t bh[2][4], bl[2][4];
            #pragma unroll
            for (int bp = 0; bp < 2; bp++) {
                uint32_t rb = st + b_off + bp * (16 * LDB) + ks * 32;
                LDSM4(bh[bp], rb);
                LDSM4(bl[bp], rb + TILE_B);
            }
            #pragma unroll
            for (int mf = 0; mf < 4; mf++) {
                #pragma unroll
                for (int nf = 0; nf < 4; nf++) {
                    const int bi = nf >> 1, sub = (nf & 1) * 2;
                    MMA(acc[mf][nf], ah[mf], bh[bi][sub], bh[bi][sub + 1]);
                    MMA(acc[mf][nf], ah[mf], bl[bi][sub], bl[bi][sub + 1]);
                    MMA(acc[mf][nf], al[mf], bh[bi][sub], bh[bi][sub + 1]);
                }
            }
        }
    };

    LOAD(0, 0);
    for (int kc = 0; kc < GNK; kc++) {
        if (kc + 1 < GNK) {
            LOAD((kc + 1) & 1, (kc + 1) * GBK);
            asm volatile("cp.async.wait_group 1;" ::: "memory");
        } else {
            asm volatile("cp.async.wait_group 0;" ::: "memory");
        }
        __syncthreads();
        COMPUTE(kc & 1);
        __syncthreads();
    }

    // epilogue
    #pragma unroll
    for (int mf = 0; mf < 4; mf++) {
        int rg = row0 + wm + mf * 16 + (lane >> 2);
        #pragma unroll
        for (int nf = 0; nf < 4; nf++) {
            int col = col0 + wn + nf * 8 + (lane & 3) * 2;
            float bx = bias ? bias[col] : 0.f;
            float by = bias ? bias[col + 1] : 0.f;
            if (rg < M) {
                float2 v = make_float2(acc[mf][nf][0] + bx, acc[mf][nf][1] + by);
                *(float2*)(C + (size_t)rg * EMB + col) = v;
            }
            if (rg + 8 < M) {
                float2 v = make_float2(acc[mf][nf][2] + bx, acc[mf][nf][3] + by);
                *(float2*)(C + (size_t)(rg + 8) * EMB + col) = v;
            }
        }
    }
}

// ---------------- RoPE (in place on g_q, g_k) ----------------
__global__ void rope_kernel(const float* __restrict__ cosb,
                            const float* __restrict__ sinb, int T)
{
    int idx = blockIdx.x * blockDim.x + threadIdx.x;
    int total = T * NH * 32;
    if (idx >= total) return;
    int i = idx & 31;
    int h = (idx >> 5) & 15;
    int t = idx >> 9;
    float c = cosb[t * DH + i];
    float s = sinb[t * DH + i];
    size_t base = (size_t)t * EMB + h * DH;
    float q0 = g_q[base + i], q1 = g_q[base + i + 32];
    g_q[base + i]      = q0 * c - q1 * s;
    g_q[base + i + 32] = q1 * c + q0 * s;
    float k0 = g_k[base + i], k1 = g_k[base + i + 32];
    g_k[base + i]      = k0 * c - k1 * s;
    g_k[base + i + 32] = k1 * c + k0 * s;
}

// ---------------- varlen causal flash attention (fp32) ----------------
#define AQ 128
#define AK 64
#define QPAD 68

__global__ __launch_bounds__(128) void attn_kernel()
{
    extern __shared__ float sm[];
    float* Qs = sm;
    float* Ks = sm + AQ * QPAD;
    float* Vs = Ks + AK * DH;

    const int b = blockIdx.z, h = blockIdx.y, qt = blockIdx.x;
    const int s0 = g_cu[b];
    const int L = g_cu[b + 1] - s0;
    const int q0 = qt * AQ;
    if (q0 >= L) return;
    const int tid = threadIdx.x;

    #pragma unroll
    for (int it = 0; it < 16; it++) {
        int f4 = it * 128 + tid;
        int r = f4 >> 4, c4 = f4 & 15;
        float4 v = make_float4(0.f, 0.f, 0.f, 0.f);
        if (q0 + r < L)
            v = *(const float4*)(g_q + (size_t)(s0 + q0 + r) * EMB + h * DH + c4 * 4);
        *(float4*)(Qs + r * QPAD + c4 * 4) = v;
    }

    const int grow = q0 + tid;
    const bool qv = grow < L;
    float m = -1e30f, l = 0.f;
    float acc[DH];
    #pragma unroll
    for (int d = 0; d < DH; d++) acc[d] = 0.f;

    const int kend = min(q0 + AQ, L);
    const int nkt = (kend + AK - 1) / AK;

    for (int kt = 0; kt < nkt; kt++) {
        __syncthreads();
        #pragma unroll
        for (int it = 0; it < 8; it++) {
            int f4 = it * 128 + tid;
            int r = f4 >> 4, c4 = f4 & 15;
            int krow = kt * AK + r;
            float4 kv = make_float4(0.f, 0.f, 0.f, 0.f);
            float4 vv = make_float4(0.f, 0.f, 0.f, 0.f);
            if (krow < L) {
                kv = *(const float4*)(g_k + (size_t)(s0 + krow) * EMB + h * DH + c4 * 4);
                vv = *(const float4*)(g_v + (size_t)(s0 + krow) * EMB + h * DH + c4 * 4);
            }
            *(float4*)(Ks + r * DH + c4 * 4) = kv;
            *(float4*)(Vs + r * DH + c4 * 4) = vv;
        }
        __syncthreads();

        if (!qv || kt * AK > grow) continue;

        float s[AK];
        #pragma unroll
        for (int j = 0; j < AK; j++) s[j] = 0.f;

        #pragma unroll
        for (int d0 = 0; d0 < DH; d0 += 16) {
            float4 q4[4];
            #pragma unroll
            for (int t4 = 0; t4 < 4; t4++)
                q4[t4] = *(const float4*)(Qs + tid * QPAD + d0 + t4 * 4);
            #pragma unroll
            for (int j = 0; j < AK; j++) {
                float sum = 0.f;
                #pragma unroll
                for (int t4 = 0; t4 < 4; t4++) {
                    float4 k4 = *(const float4*)(Ks + j * DH + d0 + t4 * 4);
                    sum += q4[t4].x * k4.x + q4[t4].y * k4.y
                         + q4[t4].z * k4.z + q4[t4].w * k4.w;
                }
                s[j] += sum;
            }
        }

        const float scale = 0.125f;
        float mt = m;
        #pragma unroll
        for (int j = 0; j < AK; j++) {
            int jg = kt * AK + j;
            float sv = s[j] * scale;
            if (jg > grow || jg >= L) sv = -1e30f;
            s[j] = sv;
            mt = fmaxf(mt, sv);
        }
        float corr = __expf(m - mt);
        m = mt;
        l *= corr;
        #pragma unroll
        for (int d = 0; d < DH; d++) acc[d] *= corr;

        #pragma unroll
        for (int j = 0; j < AK; j++) {
            float p = __expf(s[j] - m);
            l += p;
            #pragma unroll
            for (int d4 = 0; d4 < 16; d4++) {
                float4 v4 = *(const float4*)(Vs + j * DH + d4 * 4);
                acc[d4 * 4 + 0] += p * v4.x;
                acc[d4 * 4 + 1] += p * v4.y;
                acc[d4 * 4 + 2] += p * v4.z;
                acc[d4 * 4 + 3] += p * v4.w;
            }
        }
    }

    if (qv) {
        float inv = 1.f / l;
        #pragma unroll
        for (int d4 = 0; d4 < 16; d4++) {
            float4 o;
            o.x = acc[d4 * 4 + 0] * inv;
            o.y = acc[d4 * 4 + 1] * inv;
            o.z = acc[d4 * 4 + 2] * inv;
            o.w = acc[d4 * 4 + 3] * inv;
            *(float4*)(g_attn + (size_t)(s0 + grow) * EMB + h * DH + d4 * 4) = o;
        }
    }
}

// ---------------- launch ----------------
extern "C" void kernel_launch(void* const* d_in, const int* in_sizes, int n_in,
                              void* d_out, int out_size)
{
    const float* hidden = (const float*)d_in[0];
    const float* cosb   = (const float*)d_in[1];
    const float* sinb   = (const float*)d_in[2];
    const float* q_w    = (const float*)d_in[3];
    const float* q_b    = (const float*)d_in[4];
    const float* k_w    = (const float*)d_in[5];
    const float* v_w    = (const float*)d_in[6];
    const float* v_b    = (const float*)d_in[7];
    const float* out_w  = (const float*)d_in[8];
    const float* out_b  = (const float*)d_in[9];
    const int*   seqlen = (const int*)d_in[10];
    float* out = (float*)d_out;

    const int T = in_sizes[0] / EMB;
    const int B = in_sizes[10];

    float *dq, *dk, *dv, *dattn;
    cudaGetSymbolAddress((void**)&dq, g_q);
    cudaGetSymbolAddress((void**)&dk, g_k);
    cudaGetSymbolAddress((void**)&dv, g_v);
    cudaGetSymbolAddress((void**)&dattn, g_attn);
    __nv_bfloat16 *hh, *hl, *wh, *wl, *ah, *al;
    cudaGetSymbolAddress((void**)&hh, g_hid_hi);
    cudaGetSymbolAddress((void**)&hl, g_hid_lo);
    cudaGetSymbolAddress((void**)&wh, g_w_hi);
    cudaGetSymbolAddress((void**)&wl, g_w_lo);
    cudaGetSymbolAddress((void**)&ah, g_at_hi);
    cudaGetSymbolAddress((void**)&al, g_at_lo);

    cu_seqlen_kernel<<<1, 32>>>(seqlen, B);

    // split conversions
    const int WN4 = EMB * EMB / 4;
    int hn4 = T * EMB / 4;
    cvt_split4<<<(hn4 + 255) / 256, 256>>>(hidden, hh, hl, hn4);
    cvt_split4<<<(WN4 + 255) / 256, 256>>>(q_w,   wh + 0 * (size_t)EMB * EMB, wl + 0 * (size_t)EMB * EMB, WN4);
    cvt_split4<<<(WN4 + 255) / 256, 256>>>(k_w,   wh + 1 * (size_t)EMB * EMB, wl + 1 * (size_t)EMB * EMB, WN4);
    cvt_split4<<<(WN4 + 255) / 256, 256>>>(v_w,   wh + 2 * (size_t)EMB * EMB, wl + 2 * (size_t)EMB * EMB, WN4);
    cvt_split4<<<(WN4 + 255) / 256, 256>>>(out_w, wh + 3 * (size_t)EMB * EMB, wl + 3 * (size_t)EMB * EMB, WN4);

    cudaFuncSetAttribute(gemm_mma, cudaFuncAttributeMaxDynamicSharedMemorySize, GEMM_SMEM);
    dim3 gg(EMB / 128, (T + 127) / 128);
    gemm_mma<<<gg, 256, GEMM_SMEM>>>(hh, hl, wh + 0 * (size_t)EMB * EMB, wl + 0 * (size_t)EMB * EMB, q_b, dq, T);
    gemm_mma<<<gg, 256, GEMM_SMEM>>>(hh, hl, wh + 1 * (size_t)EMB * EMB, wl + 1 * (size_t)EMB * EMB, nullptr, dk, T);
    gemm_mma<<<gg, 256, GEMM_SMEM>>>(hh, hl, wh + 2 * (size_t)EMB * EMB, wl + 2 * (size_t)EMB * EMB, v_b, dv, T);

    int rope_total = T * NH * 32;
    rope_kernel<<<(rope_total + 255) / 256, 256>>>(cosb, sinb, T);

    int smem = (AQ * QPAD + 2 * AK * DH) * sizeof(float);
    cudaFuncSetAttribute(attn_kernel, cudaFuncAttributeMaxDynamicSharedMemorySize, smem);
    dim3 ga(1024 / AQ, NH, B);
    attn_kernel<<<ga, 128, smem>>>();

    cvt_split4<<<(hn4 + 255) / 256, 256>>>(dattn, ah, al, hn4);
    gemm_mma<<<gg, 256, GEMM_SMEM>>>(ah, al, wh + 3 * (size_t)EMB * EMB, wl + 3 * (size_t)EMB * EMB, out_b, out, T);
}

// round 7
// speedup vs baseline: 3.4039x; 2.1013x over previous
#include <cuda_runtime.h>
#include <cuda_bf16.h>
#include <math.h>
#include <stdint.h>

#define T_MAX 9792
#define EMB 1024
#define NH 16
#define DH 64

// ---------------- scratch (device globals; no allocs allowed) ----------------
__device__ float g_q[(size_t)T_MAX * EMB];
__device__ float g_k[(size_t)T_MAX * EMB];
__device__ float g_v[(size_t)T_MAX * EMB];
__device__ int   g_cu[64];

__device__ __nv_bfloat16 g_hid_hi[(size_t)T_MAX * EMB];
__device__ __nv_bfloat16 g_hid_lo[(size_t)T_MAX * EMB];
__device__ __nv_bfloat16 g_w_hi[(size_t)4 * EMB * EMB];
__device__ __nv_bfloat16 g_w_lo[(size_t)4 * EMB * EMB];
__device__ __nv_bfloat16 g_at_hi[(size_t)T_MAX * EMB];
__device__ __nv_bfloat16 g_at_lo[(size_t)T_MAX * EMB];
// split rope'd q/k and v
__device__ __nv_bfloat16 g_qs_hi[(size_t)T_MAX * EMB];
__device__ __nv_bfloat16 g_qs_lo[(size_t)T_MAX * EMB];
__device__ __nv_bfloat16 g_ks_hi[(size_t)T_MAX * EMB];
__device__ __nv_bfloat16 g_ks_lo[(size_t)T_MAX * EMB];
__device__ __nv_bfloat16 g_vs_hi[(size_t)T_MAX * EMB];
__device__ __nv_bfloat16 g_vs_lo[(size_t)T_MAX * EMB];

// ---------------- PTX helpers ----------------
__device__ __forceinline__ uint32_t smem_u32(const void* p) {
    uint32_t a;
    asm("{ .reg .u64 t; cvta.to.shared.u64 t, %1; cvt.u32.u64 %0, t; }" : "=r"(a) : "l"(p));
    return a;
}

#define CPA(dst, src) \
    asm volatile("cp.async.cg.shared.global [%0], [%1], 16;" :: "r"(dst), "l"(src) : "memory")
#define CPA_COMMIT() asm volatile("cp.async.commit_group;" ::: "memory")

#define LDSM4(r, addr) \
    asm volatile("ldmatrix.sync.aligned.m8n8.x4.shared.b16 {%0,%1,%2,%3}, [%4];" \
        : "=r"((r)[0]), "=r"((r)[1]), "=r"((r)[2]), "=r"((r)[3]) : "r"(addr))
#define LDSM4T(r, addr) \
    asm volatile("ldmatrix.sync.aligned.m8n8.x4.trans.shared.b16 {%0,%1,%2,%3}, [%4];" \
        : "=r"((r)[0]), "=r"((r)[1]), "=r"((r)[2]), "=r"((r)[3]) : "r"(addr))

#define MMA(c, a, b0, b1) \
    asm volatile("mma.sync.aligned.m16n8k16.row.col.f32.bf16.bf16.f32 " \
        "{%0,%1,%2,%3}, {%4,%5,%6,%7}, {%8,%9}, {%0,%1,%2,%3};" \
        : "+f"((c)[0]), "+f"((c)[1]), "+f"((c)[2]), "+f"((c)[3]) \
        : "r"((a)[0]), "r"((a)[1]), "r"((a)[2]), "r"((a)[3]), "r"(b0), "r"(b1))

__device__ __forceinline__ uint32_t pack_bf2(float x, float y) {
    __nv_bfloat162 t = __floats2bfloat162_rn(x, y);
    return *(uint32_t*)&t;
}
__device__ __forceinline__ uint32_t pack_bf2_res(float x, float y, uint32_t hi) {
    __nv_bfloat162 h = *(__nv_bfloat162*)&hi;
    return pack_bf2(x - __bfloat162float(h.x), y - __bfloat162float(h.y));
}

// ---------------- cumulative sequence lengths ----------------
__global__ void cu_seqlen_kernel(const int* __restrict__ seq_len, int B) {
    if (threadIdx.x == 0 && blockIdx.x == 0) {
        int s = 0;
        g_cu[0] = 0;
        for (int b = 0; b < B; b++) { s += seq_len[b]; g_cu[b + 1] = s; }
    }
}

// ---------------- fp32 -> (bf16 hi, bf16 lo) split ----------------
__global__ void cvt_split4(const float* __restrict__ x,
                           __nv_bfloat16* __restrict__ hi,
                           __nv_bfloat16* __restrict__ lo, int n4)
{
    int i = blockIdx.x * blockDim.x + threadIdx.x;
    if (i >= n4) return;
    float4 v = ((const float4*)x)[i];
    __nv_bfloat16 h0 = __float2bfloat16(v.x);
    __nv_bfloat16 h1 = __float2bfloat16(v.y);
    __nv_bfloat16 h2 = __float2bfloat16(v.z);
    __nv_bfloat16 h3 = __float2bfloat16(v.w);
    __nv_bfloat16 l0 = __float2bfloat16(v.x - __bfloat162float(h0));
    __nv_bfloat16 l1 = __float2bfloat16(v.y - __bfloat162float(h1));
    __nv_bfloat16 l2 = __float2bfloat16(v.z - __bfloat162float(h2));
    __nv_bfloat16 l3 = __float2bfloat16(v.w - __bfloat162float(h3));
    __nv_bfloat162* hp = (__nv_bfloat162*)hi;
    __nv_bfloat162* lp = (__nv_bfloat162*)lo;
    hp[2 * i]     = __halves2bfloat162(h0, h1);
    hp[2 * i + 1] = __halves2bfloat162(h2, h3);
    lp[2 * i]     = __halves2bfloat162(l0, l1);
    lp[2 * i + 1] = __halves2bfloat162(l2, l3);
}

// ---------------- mma.sync GEMM (unchanged from R6, passing) ----------------
#define GBK 32
#define GNK (EMB / GBK)
#define LDB 80
#define TILE_B (128 * LDB)
#define STG_B (4 * TILE_B)
#define GEMM_SMEM (2 * STG_B)

__global__ __launch_bounds__(256, 1)
void gemm_mma(const __nv_bfloat16* __restrict__ Ahi, const __nv_bfloat16* __restrict__ Alo,
              const __nv_bfloat16* __restrict__ Whi, const __nv_bfloat16* __restrict__ Wlo,
              const float* __restrict__ bias, float* __restrict__ C, int M)
{
    extern __shared__ char smem[];
    const uint32_t sbase = smem_u32(smem);
    const int tid = threadIdx.x;
    const int wid = tid >> 5, lane = tid & 31;
    const int row0 = blockIdx.y * 128, col0 = blockIdx.x * 128;
    const int wm = (wid >> 2) * 64, wn = (wid & 3) * 32;

    float acc[4][4][4];
    #pragma unroll
    for (int i = 0; i < 4; i++)
        #pragma unroll
        for (int j = 0; j < 4; j++)
            #pragma unroll
            for (int k = 0; k < 4; k++) acc[i][j][k] = 0.f;

    const int r_ld[2]  = { tid >> 2, (tid + 256) >> 2 };
    const int cb_ld    = (tid & 3) * 16;
    const int ce_ld    = (tid & 3) * 8;

    auto LOAD = [&](int s, int k0) {
        #pragma unroll
        for (int h = 0; h < 2; h++) {
            int r = r_ld[h];
            uint32_t d = sbase + s * STG_B + r * LDB + cb_ld;
            int ga = min(row0 + r, M - 1);
            int gb = col0 + r;
            CPA(d,              Ahi + (size_t)ga * EMB + k0 + ce_ld);
            CPA(d + TILE_B,     Alo + (size_t)ga * EMB + k0 + ce_ld);
            CPA(d + 2 * TILE_B, Whi + (size_t)gb * EMB + k0 + ce_ld);
            CPA(d + 3 * TILE_B, Wlo + (size_t)gb * EMB + k0 + ce_ld);
        }
        CPA_COMMIT();
    };

    const uint32_t a_off = (uint32_t)((wm + (lane & 15)) * LDB + (lane >> 4) * 16);
    const uint32_t b_off = (uint32_t)(2 * TILE_B +
                         (wn + ((lane >> 4) << 3) + (lane & 7)) * LDB + ((lane >> 3) & 1) * 16);

    auto COMPUTE = [&](int s) {
        const uint32_t st = sbase + s * STG_B;
        #pragma unroll
        for (int ks = 0; ks < 2; ks++) {
            uint32_t ah[4][4], al[4][4];
            #pragma unroll
            for (int mf = 0; mf < 4; mf++) {
                uint32_t ra = st + a_off + mf * (16 * LDB) + ks * 32;
                LDSM4(ah[mf], ra);
                LDSM4(al[mf], ra + TILE_B);
            }
            uint32_t bh[2][4], bl[2][4];
            #pragma unroll
            for (int bp = 0; bp < 2; bp++) {
                uint32_t rb = st + b_off + bp * (16 * LDB) + ks * 32;
                LDSM4(bh[bp], rb);
                LDSM4(bl[bp], rb + TILE_B);
            }
            #pragma unroll
            for (int mf = 0; mf < 4; mf++) {
                #pragma unroll
                for (int nf = 0; nf < 4; nf++) {
                    const int bi = nf >> 1, sub = (nf & 1) * 2;
                    MMA(acc[mf][nf], ah[mf], bh[bi][sub], bh[bi][sub + 1]);
                    MMA(acc[mf][nf], ah[mf], bl[bi][sub], bl[bi][sub + 1]);
                    MMA(acc[mf][nf], al[mf], bh[bi][sub], bh[bi][sub + 1]);
                }
            }
        }
    };

    LOAD(0, 0);
    for (int kc = 0; kc < GNK; kc++) {
        if (kc + 1 < GNK) {
            LOAD((kc + 1) & 1, (kc + 1) * GBK);
            asm volatile("cp.async.wait_group 1;" ::: "memory");
        } else {
            asm volatile("cp.async.wait_group 0;" ::: "memory");
        }
        __syncthreads();
        COMPUTE(kc & 1);
        __syncthreads();
    }

    #pragma unroll
    for (int mf = 0; mf < 4; mf++) {
        int rg = row0 + wm + mf * 16 + (lane >> 2);
        #pragma unroll
        for (int nf = 0; nf < 4; nf++) {
            int col = col0 + wn + nf * 8 + (lane & 3) * 2;
            float bx = bias ? bias[col] : 0.f;
            float by = bias ? bias[col + 1] : 0.f;
            if (rg < M) {
                float2 v = make_float2(acc[mf][nf][0] + bx, acc[mf][nf][1] + by);
                *(float2*)(C + (size_t)rg * EMB + col) = v;
            }
            if (rg + 8 < M) {
                float2 v = make_float2(acc[mf][nf][2] + bx, acc[mf][nf][3] + by);
                *(float2*)(C + (size_t)(rg + 8) * EMB + col) = v;
            }
        }
    }
}

// ---------------- RoPE + bf16 split for q,k,v ----------------
__global__ void rope_split(const float* __restrict__ cosb,
                           const float* __restrict__ sinb, int T)
{
    int idx = blockIdx.x * blockDim.x + threadIdx.x;
    int total = T * NH * 32;
    if (idx >= total) return;
    int i = idx & 31;
    int h = (idx >> 5) & 15;
    int t = idx >> 9;
    float c = cosb[t * DH + i];
    float s = sinb[t * DH + i];
    size_t base = (size_t)t * EMB + h * DH;

    float q0 = g_q[base + i], q1 = g_q[base + i + 32];
    float a0 = (q0 * c - q1 * s) * 0.125f;   // fold 1/sqrt(64)
    float a1 = (q1 * c + q0 * s) * 0.125f;
    __nv_bfloat16 h0 = __float2bfloat16(a0);
    __nv_bfloat16 h1 = __float2bfloat16(a1);
    g_qs_hi[base + i] = h0;
    g_qs_hi[base + i + 32] = h1;
    g_qs_lo[base + i] = __float2bfloat16(a0 - __bfloat162float(h0));
    g_qs_lo[base + i + 32] = __float2bfloat16(a1 - __bfloat162float(h1));

    float k0 = g_k[base + i], k1 = g_k[base + i + 32];
    float b0 = k0 * c - k1 * s;
    float b1 = k1 * c + k0 * s;
    h0 = __float2bfloat16(b0);
    h1 = __float2bfloat16(b1);
    g_ks_hi[base + i] = h0;
    g_ks_hi[base + i + 32] = h1;
    g_ks_lo[base + i] = __float2bfloat16(b0 - __bfloat162float(h0));
    g_ks_lo[base + i + 32] = __float2bfloat16(b1 - __bfloat162float(h1));

    float v0 = g_v[base + i], v1 = g_v[base + i + 32];
    h0 = __float2bfloat16(v0);
    h1 = __float2bfloat16(v1);
    g_vs_hi[base + i] = h0;
    g_vs_hi[base + i + 32] = h1;
    g_vs_lo[base + i] = __float2bfloat16(v0 - __bfloat162float(h0));
    g_vs_lo[base + i + 32] = __float2bfloat16(v1 - __bfloat162float(h1));
}

// ---------------- mma flash attention ----------------
// CTA: 8 warps, 128 q rows (16/warp). ktile = 64 keys. DH = 64.
#define PADS 72                 // bf16 row stride (144B, 16B-aligned, conflict-free)
#define QH_OFF 0
#define QL_OFF (128 * PADS)
#define KH_OFF (2 * 128 * PADS)
#define KL_OFF (KH_OFF + 64 * PADS)
#define VH_OFF (KL_OFF + 64 * PADS)
#define VL_OFF (VH_OFF + 64 * PADS)
#define ATT_SMEM ((VL_OFF + 64 * PADS) * 2)

__global__ __launch_bounds__(256, 1) void attn_mma(int T)
{
    extern __shared__ char smc[];
    const uint32_t sb = smem_u32(smc);
    const int b = blockIdx.z, h = blockIdx.y, qt = blockIdx.x;
    const int s0 = g_cu[b];
    const int L = g_cu[b + 1] - s0;
    const int q0 = qt * 128;
    if (q0 >= L) return;
    const int tid = threadIdx.x, wid = tid >> 5, lane = tid & 31;

    // ---- load Q (hi+lo) ----
    {
        #pragma unroll
        for (int it = 0; it < 4; it++) {
            int ch = it * 256 + tid;          // 1024 chunks
            int r = ch >> 3, c = ch & 7;
            int gr = min(s0 + q0 + r, T - 1);
            size_t go = (size_t)gr * EMB + h * DH + c * 8;
            uint32_t d = sb + (r * PADS + c * 8) * 2;
            CPA(d + QH_OFF * 2, g_qs_hi + go);
            CPA(d + QL_OFF * 2, g_qs_lo + go);
        }
        CPA_COMMIT();
        asm volatile("cp.async.wait_group 0;" ::: "memory");
        __syncthreads();
    }

    // hoist Q fragments (A operand, row = wid*16 + ...)
    uint32_t qh[4][4], ql[4][4];
    {
        uint32_t qa = sb + ((wid * 16 + (lane & 15)) * PADS) * 2 + (lane >> 4) * 16;
        #pragma unroll
        for (int ks = 0; ks < 4; ks++) {
            LDSM4(qh[ks], qa + QH_OFF * 2 + ks * 32);
            LDSM4(ql[ks], qa + QL_OFF * 2 + ks * 32);
        }
    }

    const int row0 = q0 + wid * 16 + (lane >> 2);
    const int row1 = row0 + 8;
    float m0_ = -1e30f, m1_ = -1e30f, l0_ = 0.f, l1_ = 0.f;
    float oacc[8][4];
    #pragma unroll
    for (int i = 0; i < 8; i++)
        #pragma unroll
        for (int j = 0; j < 4; j++) oacc[i][j] = 0.f;

    const int nkt = (min(q0 + 128, L) + 63) >> 6;
    const int wrow_max = q0 + wid * 16 + 15;

    const uint32_t kaddr = sb + ((((lane >> 4) << 3) + (lane & 7)) * PADS) * 2 + ((lane >> 3) & 1) * 16;
    const uint32_t vaddr = sb + ((lane & 15) * PADS + ((lane >> 4) << 3)) * 2;

    for (int kt = 0; kt < nkt; kt++) {
        __syncthreads();
        // ---- load K,V (hi+lo) tiles: 64 rows ----
        #pragma unroll
        for (int it = 0; it < 2; it++) {
            int ch = it * 256 + tid;          // 512 chunks per buffer
            int r = ch >> 3, c = ch & 7;
            int gr = min(s0 + kt * 64 + r, T - 1);
            size_t go = (size_t)gr * EMB + h * DH + c * 8;
            uint32_t d = sb + (r * PADS + c * 8) * 2;
            CPA(d + KH_OFF * 2, g_ks_hi + go);
            CPA(d + KL_OFF * 2, g_ks_lo + go);
            CPA(d + VH_OFF * 2, g_vs_hi + go);
            CPA(d + VL_OFF * 2, g_vs_lo + go);
        }
        CPA_COMMIT();
        asm volatile("cp.async.wait_group 0;" ::: "memory");
        __syncthreads();

        if (kt * 64 > wrow_max) continue;   // fully masked for this warp

        // ---- S = Q K^T (3-product emulation) ----
        float sacc[8][4];
        #pragma unroll
        for (int i = 0; i < 8; i++)
            #pragma unroll
            for (int j = 0; j < 4; j++) sacc[i][j] = 0.f;

        #pragma unroll
        for (int bp = 0; bp < 4; bp++) {
            #pragma unroll
            for (int ks = 0; ks < 4; ks++) {
                uint32_t kh4[4], kl4[4];
                uint32_t ka = kaddr + (bp * 16 * PADS) * 2 + ks * 32;
                LDSM4(kh4, ka + KH_OFF * 2);
                LDSM4(kl4, ka + KL_OFF * 2);
                MMA(sacc[bp * 2], qh[ks], kh4[0], kh4[1]);
                MMA(sacc[bp * 2], qh[ks], kl4[0], kl4[1]);
                MMA(sacc[bp * 2], ql[ks], kh4[0], kh4[1]);
                MMA(sacc[bp * 2 + 1], qh[ks], kh4[2], kh4[3]);
                MMA(sacc[bp * 2 + 1], qh[ks], kl4[2], kl4[3]);
                MMA(sacc[bp * 2 + 1], ql[ks], kh4[2], kh4[3]);
            }
        }

        // ---- mask + online softmax ----
        float mx0 = -1e30f, mx1 = -1e30f;
        #pragma unroll
        for (int nf = 0; nf < 8; nf++) {
            int c0 = kt * 64 + nf * 8 + (lane & 3) * 2;
            int c1 = c0 + 1;
            if (c0 > row0 || c0 >= L) sacc[nf][0] = -1e30f;
            if (c1 > row0 || c1 >= L) sacc[nf][1] = -1e30f;
            if (c0 > row1 || c0 >= L) sacc[nf][2] = -1e30f;
            if (c1 > row1 || c1 >= L) sacc[nf][3] = -1e30f;
            mx0 = fmaxf(mx0, fmaxf(sacc[nf][0], sacc[nf][1]));
            mx1 = fmaxf(mx1, fmaxf(sacc[nf][2], sacc[nf][3]));
        }
        mx0 = fmaxf(mx0, __shfl_xor_sync(~0u, mx0, 1));
        mx0 = fmaxf(mx0, __shfl_xor_sync(~0u, mx0, 2));
        mx1 = fmaxf(mx1, __shfl_xor_sync(~0u, mx1, 1));
        mx1 = fmaxf(mx1, __shfl_xor_sync(~0u, mx1, 2));
        float mn0 = fmaxf(m0_, mx0), mn1 = fmaxf(m1_, mx1);
        float corr0 = __expf(m0_ - mn0), corr1 = __expf(m1_ - mn1);
        m0_ = mn0; m1_ = mn1;

        float ls0 = 0.f, ls1 = 0.f;
        #pragma unroll
        for (int nf = 0; nf < 8; nf++) {
            sacc[nf][0] = __expf(sacc[nf][0] - mn0);
            sacc[nf][1] = __expf(sacc[nf][1] - mn0);
            sacc[nf][2] = __expf(sacc[nf][2] - mn1);
            sacc[nf][3] = __expf(sacc[nf][3] - mn1);
            ls0 += sacc[nf][0] + sacc[nf][1];
            ls1 += sacc[nf][2] + sacc[nf][3];
        }
        ls0 += __shfl_xor_sync(~0u, ls0, 1);
        ls0 += __shfl_xor_sync(~0u, ls0, 2);
        ls1 += __shfl_xor_sync(~0u, ls1, 1);
        ls1 += __shfl_xor_sync(~0u, ls1, 2);
        l0_ = l0_ * corr0 + ls0;
        l1_ = l1_ * corr1 + ls1;

        #pragma unroll
        for (int nf = 0; nf < 8; nf++) {
            oacc[nf][0] *= corr0; oacc[nf][1] *= corr0;
            oacc[nf][2] *= corr1; oacc[nf][3] *= corr1;
        }

        // ---- O += P V (3-product emulation) ----
        #pragma unroll
        for (int kk = 0; kk < 4; kk++) {
            uint32_t ph[4], pl[4];
            ph[0] = pack_bf2(sacc[2 * kk][0], sacc[2 * kk][1]);
            ph[1] = pack_bf2(sacc[2 * kk][2], sacc[2 * kk][3]);
            ph[2] = pack_bf2(sacc[2 * kk + 1][0], sacc[2 * kk + 1][1]);
            ph[3] = pack_bf2(sacc[2 * kk + 1][2], sacc[2 * kk + 1][3]);
            pl[0] = pack_bf2_res(sacc[2 * kk][0], sacc[2 * kk][1], ph[0]);
            pl[1] = pack_bf2_res(sacc[2 * kk][2], sacc[2 * kk][3], ph[1]);
            pl[2] = pack_bf2_res(sacc[2 * kk + 1][0], sacc[2 * kk + 1][1], ph[2]);
            pl[3] = pack_bf2_res(sacc[2 * kk + 1][2], sacc[2 * kk + 1][3], ph[3]);
            #pragma unroll
            for (int nb = 0; nb < 4; nb++) {
                uint32_t vh4[4], vl4[4];
                uint32_t va = vaddr + (kk * 16 * PADS + nb * 16) * 2;
                LDSM4T(vh4, va + VH_OFF * 2);
                LDSM4T(vl4, va + VL_OFF * 2);
                MMA(oacc[nb * 2], ph, vh4[0], vh4[1]);
                MMA(oacc[nb * 2], ph, vl4[0], vl4[1]);
                MMA(oacc[nb * 2], pl, vh4[0], vh4[1]);
                MMA(oacc[nb * 2 + 1], ph, vh4[2], vh4[3]);
                MMA(oacc[nb * 2 + 1], ph, vl4[2], vl4[3]);
                MMA(oacc[nb * 2 + 1], pl, vh4[2], vh4[3]);
            }
        }
    }

    // ---- epilogue: normalize, split to bf16 hi/lo ----
    if (row0 < L) {
        float inv = 1.f / l0_;
        #pragma unroll
        for (int nf = 0; nf < 8; nf++) {
            float o0 = oacc[nf][0] * inv, o1 = oacc[nf][1] * inv;
            uint32_t hi = pack_bf2(o0, o1);
            uint32_t lo = pack_bf2_res(o0, o1, hi);
            size_t off = (size_t)(s0 + row0) * EMB + h * DH + nf * 8 + (lane & 3) * 2;
            *(uint32_t*)(g_at_hi + off) = hi;
            *(uint32_t*)(g_at_lo + off) = lo;
        }
    }
    if (row1 < L) {
        float inv = 1.f / l1_;
        #pragma unroll
        for (int nf = 0; nf < 8; nf++) {
            float o0 = oacc[nf][2] * inv, o1 = oacc[nf][3] * inv;
            uint32_t hi = pack_bf2(o0, o1);
            uint32_t lo = pack_bf2_res(o0, o1, hi);
            size_t off = (size_t)(s0 + row1) * EMB + h * DH + nf * 8 + (lane & 3) * 2;
            *(uint32_t*)(g_at_hi + off) = hi;
            *(uint32_t*)(g_at_lo + off) = lo;
        }
    }
}

// ---------------- launch ----------------
extern "C" void kernel_launch(void* const* d_in, const int* in_sizes, int n_in,
                              void* d_out, int out_size)
{
    const float* hidden = (const float*)d_in[0];
    const float* cosb   = (const float*)d_in[1];
    const float* sinb   = (const float*)d_in[2];
    const float* q_w    = (const float*)d_in[3];
    const float* q_b    = (const float*)d_in[4];
    const float* k_w    = (const float*)d_in[5];
    const float* v_w    = (const float*)d_in[6];
    const float* v_b    = (const float*)d_in[7];
    const float* out_w  = (const float*)d_in[8];
    const float* out_b  = (const float*)d_in[9];
    const int*   seqlen = (const int*)d_in[10];
    float* out = (float*)d_out;

    const int T = in_sizes[0] / EMB;
    const int B = in_sizes[10];

    float *dq, *dk, *dv;
    cudaGetSymbolAddress((void**)&dq, g_q);
    cudaGetSymbolAddress((void**)&dk, g_k);
    cudaGetSymbolAddress((void**)&dv, g_v);
    __nv_bfloat16 *hh, *hl, *wh, *wl, *ah, *al;
    cudaGetSymbolAddress((void**)&hh, g_hid_hi);
    cudaGetSymbolAddress((void**)&hl, g_hid_lo);
    cudaGetSymbolAddress((void**)&wh, g_w_hi);
    cudaGetSymbolAddress((void**)&wl, g_w_lo);
    cudaGetSymbolAddress((void**)&ah, g_at_hi);
    cudaGetSymbolAddress((void**)&al, g_at_lo);

    cu_seqlen_kernel<<<1, 32>>>(seqlen, B);

    const int WN4 = EMB * EMB / 4;
    int hn4 = T * EMB / 4;
    cvt_split4<<<(hn4 + 255) / 256, 256>>>(hidden, hh, hl, hn4);
    cvt_split4<<<(WN4 + 255) / 256, 256>>>(q_w,   wh + 0 * (size_t)EMB * EMB, wl + 0 * (size_t)EMB * EMB, WN4);
    cvt_split4<<<(WN4 + 255) / 256, 256>>>(k_w,   wh + 1 * (size_t)EMB * EMB, wl + 1 * (size_t)EMB * EMB, WN4);
    cvt_split4<<<(WN4 + 255) / 256, 256>>>(v_w,   wh + 2 * (size_t)EMB * EMB, wl + 2 * (size_t)EMB * EMB, WN4);
    cvt_split4<<<(WN4 + 255) / 256, 256>>>(out_w, wh + 3 * (size_t)EMB * EMB, wl + 3 * (size_t)EMB * EMB, WN4);

    cudaFuncSetAttribute(gemm_mma, cudaFuncAttributeMaxDynamicSharedMemorySize, GEMM_SMEM);
    dim3 gg(EMB / 128, (T + 127) / 128);
    gemm_mma<<<gg, 256, GEMM_SMEM>>>(hh, hl, wh + 0 * (size_t)EMB * EMB, wl + 0 * (size_t)EMB * EMB, q_b, dq, T);
    gemm_mma<<<gg, 256, GEMM_SMEM>>>(hh, hl, wh + 1 * (size_t)EMB * EMB, wl + 1 * (size_t)EMB * EMB, nullptr, dk, T);
    gemm_mma<<<gg, 256, GEMM_SMEM>>>(hh, hl, wh + 2 * (size_t)EMB * EMB, wl + 2 * (size_t)EMB * EMB, v_b, dv, T);

    int rope_total = T * NH * 32;
    rope_split<<<(rope_total + 255) / 256, 256>>>(cosb, sinb, T);

    cudaFuncSetAttribute(attn_mma, cudaFuncAttributeMaxDynamicSharedMemorySize, ATT_SMEM);
    dim3 ga(1024 / 128, NH, B);
    attn_mma<<<ga, 256, ATT_SMEM>>>(T);

    gemm_mma<<<gg, 256, GEMM_SMEM>>>(ah, al, wh + 3 * (size_t)EMB * EMB, wl + 3 * (size_t)EMB * EMB, out_b, out, T);
}

// round 9
// speedup vs baseline: 3.7232x; 1.0938x over previous
#include <cuda_runtime.h>
#include <cuda_bf16.h>
#include <cuda_fp16.h>
#include <math.h>
#include <stdint.h>

#define T_MAX 9792
#define EMB 1024
#define NH 16
#define DH 64

// ---------------- scratch (device globals; no allocs allowed) ----------------
__device__ float g_q[(size_t)T_MAX * EMB];
__device__ float g_k[(size_t)T_MAX * EMB];
__device__ float g_v[(size_t)T_MAX * EMB];
__device__ int   g_cu[64];

__device__ __nv_bfloat16 g_hid_hi[(size_t)T_MAX * EMB];
__device__ __nv_bfloat16 g_hid_lo[(size_t)T_MAX * EMB];
__device__ __nv_bfloat16 g_w_hi[(size_t)4 * EMB * EMB];
__device__ __nv_bfloat16 g_w_lo[(size_t)4 * EMB * EMB];
__device__ __nv_bfloat16 g_at_hi[(size_t)T_MAX * EMB];
__device__ __nv_bfloat16 g_at_lo[(size_t)T_MAX * EMB];
// split rope'd q/k (bf16) and v (fp16)
__device__ __nv_bfloat16 g_qs_hi[(size_t)T_MAX * EMB];
__device__ __nv_bfloat16 g_qs_lo[(size_t)T_MAX * EMB];
__device__ __nv_bfloat16 g_ks_hi[(size_t)T_MAX * EMB];
__device__ __nv_bfloat16 g_ks_lo[(size_t)T_MAX * EMB];
__device__ __half        g_vs_hi[(size_t)T_MAX * EMB];
__device__ __half        g_vs_lo[(size_t)T_MAX * EMB];

// ---------------- PTX helpers ----------------
__device__ __forceinline__ uint32_t smem_u32(const void* p) {
    uint32_t a;
    asm("{ .reg .u64 t; cvta.to.shared.u64 t, %1; cvt.u32.u64 %0, t; }" : "=r"(a) : "l"(p));
    return a;
}

#define CPA(dst, src) \
    asm volatile("cp.async.cg.shared.global [%0], [%1], 16;" :: "r"(dst), "l"(src) : "memory")
#define CPA_COMMIT() asm volatile("cp.async.commit_group;" ::: "memory")

#define LDSM4(r, addr) \
    asm volatile("ldmatrix.sync.aligned.m8n8.x4.shared.b16 {%0,%1,%2,%3}, [%4];" \
        : "=r"((r)[0]), "=r"((r)[1]), "=r"((r)[2]), "=r"((r)[3]) : "r"(addr))
#define LDSM4T(r, addr) \
    asm volatile("ldmatrix.sync.aligned.m8n8.x4.trans.shared.b16 {%0,%1,%2,%3}, [%4];" \
        : "=r"((r)[0]), "=r"((r)[1]), "=r"((r)[2]), "=r"((r)[3]) : "r"(addr))

#define MMA(c, a, b0, b1) \
    asm volatile("mma.sync.aligned.m16n8k16.row.col.f32.bf16.bf16.f32 " \
        "{%0,%1,%2,%3}, {%4,%5,%6,%7}, {%8,%9}, {%0,%1,%2,%3};" \
        : "+f"((c)[0]), "+f"((c)[1]), "+f"((c)[2]), "+f"((c)[3]) \
        : "r"((a)[0]), "r"((a)[1]), "r"((a)[2]), "r"((a)[3]), "r"(b0), "r"(b1))

#define MMAH(c, a, b0, b1) \
    asm volatile("mma.sync.aligned.m16n8k16.row.col.f32.f16.f16.f32 " \
        "{%0,%1,%2,%3}, {%4,%5,%6,%7}, {%8,%9}, {%0,%1,%2,%3};" \
        : "+f"((c)[0]), "+f"((c)[1]), "+f"((c)[2]), "+f"((c)[3]) \
        : "r"((a)[0]), "r"((a)[1]), "r"((a)[2]), "r"((a)[3]), "r"(b0), "r"(b1))

__device__ __forceinline__ uint32_t pack_bf2(float x, float y) {
    __nv_bfloat162 t = __floats2bfloat162_rn(x, y);
    return *(uint32_t*)&t;
}
__device__ __forceinline__ uint32_t pack_bf2_res(float x, float y, uint32_t hi) {
    __nv_bfloat162 h = *(__nv_bfloat162*)&hi;
    return pack_bf2(x - __bfloat162float(h.x), y - __bfloat162float(h.y));
}
// exp2 of two fp32 values -> packed fp16x2 (lo first)
__device__ __forceinline__ uint32_t ex2h2(float lo, float hi) {
    uint32_t p, r;
    asm("cvt.rn.f16x2.f32 %0, %1, %2;" : "=r"(p) : "f"(hi), "f"(lo));
    asm("ex2.approx.f16x2 %0, %1;" : "=r"(r) : "r"(p));
    return r;
}
__device__ __forceinline__ float2 h2f2(uint32_t u) {
    __half2 h = *(__half2*)&u;
    return __half22float2(h);
}

// ---------------- cumulative sequence lengths ----------------
__global__ void cu_seqlen_kernel(const int* __restrict__ seq_len, int B) {
    if (threadIdx.x == 0 && blockIdx.x == 0) {
        int s = 0;
        g_cu[0] = 0;
        for (int b = 0; b < B; b++) { s += seq_len[b]; g_cu[b + 1] = s; }
    }
}

// ---------------- fp32 -> (bf16 hi, bf16 lo) split ----------------
__global__ void cvt_split4(const float* __restrict__ x,
                           __nv_bfloat16* __restrict__ hi,
                           __nv_bfloat16* __restrict__ lo, int n4)
{
    int i = blockIdx.x * blockDim.x + threadIdx.x;
    if (i >= n4) return;
    float4 v = ((const float4*)x)[i];
    __nv_bfloat16 h0 = __float2bfloat16(v.x);
    __nv_bfloat16 h1 = __float2bfloat16(v.y);
    __nv_bfloat16 h2 = __float2bfloat16(v.z);
    __nv_bfloat16 h3 = __float2bfloat16(v.w);
    __nv_bfloat16 l0 = __float2bfloat16(v.x - __bfloat162float(h0));
    __nv_bfloat16 l1 = __float2bfloat16(v.y - __bfloat162float(h1));
    __nv_bfloat16 l2 = __float2bfloat16(v.z - __bfloat162float(h2));
    __nv_bfloat16 l3 = __float2bfloat16(v.w - __bfloat162float(h3));
    __nv_bfloat162* hp = (__nv_bfloat162*)hi;
    __nv_bfloat162* lp = (__nv_bfloat162*)lo;
    hp[2 * i]     = __halves2bfloat162(h0, h1);
    hp[2 * i + 1] = __halves2bfloat162(h2, h3);
    lp[2 * i]     = __halves2bfloat162(l0, l1);
    lp[2 * i + 1] = __halves2bfloat162(l2, l3);
}

// ---------------- mma.sync GEMM body (3-product bf16 emulation) ----------------
#define GBK 32
#define GNK (EMB / GBK)
#define LDB 80
#define TILE_B (128 * LDB)
#define STG_B (4 * TILE_B)
#define GEMM_SMEM (2 * STG_B)

__device__ __forceinline__ void gemm_body(
    const __nv_bfloat16* __restrict__ Ahi, const __nv_bfloat16* __restrict__ Alo,
    const __nv_bfloat16* __restrict__ Whi, const __nv_bfloat16* __restrict__ Wlo,
    const float* __restrict__ bias, float* __restrict__ C, int M,
    char* smem, int bx, int by)
{
    const uint32_t sbase = smem_u32(smem);
    const int tid = threadIdx.x;
    const int wid = tid >> 5, lane = tid & 31;
    const int row0 = by * 128, col0 = bx * 128;
    const int wm = (wid >> 2) * 64, wn = (wid & 3) * 32;

    float acc[4][4][4];
    #pragma unroll
    for (int i = 0; i < 4; i++)
        #pragma unroll
        for (int j = 0; j < 4; j++)
            #pragma unroll
            for (int k = 0; k < 4; k++) acc[i][j][k] = 0.f;

    const int r_ld[2]  = { tid >> 2, (tid + 256) >> 2 };
    const int cb_ld    = (tid & 3) * 16;
    const int ce_ld    = (tid & 3) * 8;

    auto LOAD = [&](int s, int k0) {
        #pragma unroll
        for (int h = 0; h < 2; h++) {
            int r = r_ld[h];
            uint32_t d = sbase + s * STG_B + r * LDB + cb_ld;
            int ga = min(row0 + r, M - 1);
            int gb = col0 + r;
            CPA(d,              Ahi + (size_t)ga * EMB + k0 + ce_ld);
            CPA(d + TILE_B,     Alo + (size_t)ga * EMB + k0 + ce_ld);
            CPA(d + 2 * TILE_B, Whi + (size_t)gb * EMB + k0 + ce_ld);
            CPA(d + 3 * TILE_B, Wlo + (size_t)gb * EMB + k0 + ce_ld);
        }
        CPA_COMMIT();
    };

    const uint32_t a_off = (uint32_t)((wm + (lane & 15)) * LDB + (lane >> 4) * 16);
    const uint32_t b_off = (uint32_t)(2 * TILE_B +
                         (wn + ((lane >> 4) << 3) + (lane & 7)) * LDB + ((lane >> 3) & 1) * 16);

    auto COMPUTE = [&](int s) {
        const uint32_t st = sbase + s * STG_B;
        #pragma unroll
        for (int ks = 0; ks < 2; ks++) {
            uint32_t ah[4][4], al[4][4];
            #pragma unroll
            for (int mf = 0; mf < 4; mf++) {
                uint32_t ra = st + a_off + mf * (16 * LDB) + ks * 32;
                LDSM4(ah[mf], ra);
                LDSM4(al[mf], ra + TILE_B);
            }
            uint32_t bh[2][4], bl[2][4];
            #pragma unroll
            for (int bp = 0; bp < 2; bp++) {
                uint32_t rb = st + b_off + bp * (16 * LDB) + ks * 32;
                LDSM4(bh[bp], rb);
                LDSM4(bl[bp], rb + TILE_B);
            }
            #pragma unroll
            for (int mf = 0; mf < 4; mf++) {
                #pragma unroll
                for (int nf = 0; nf < 4; nf++) {
                    const int bi = nf >> 1, sub = (nf & 1) * 2;
                    MMA(acc[mf][nf], ah[mf], bh[bi][sub], bh[bi][sub + 1]);
                    MMA(acc[mf][nf], ah[mf], bl[bi][sub], bl[bi][sub + 1]);
                    MMA(acc[mf][nf], al[mf], bh[bi][sub], bh[bi][sub + 1]);
                }
            }
        }
    };

    LOAD(0, 0);
    for (int kc = 0; kc < GNK; kc++) {
        if (kc + 1 < GNK) {
            LOAD((kc + 1) & 1, (kc + 1) * GBK);
            asm volatile("cp.async.wait_group 1;" ::: "memory");
        } else {
            asm volatile("cp.async.wait_group 0;" ::: "memory");
        }
        __syncthreads();
        COMPUTE(kc & 1);
        __syncthreads();
    }

    #pragma unroll
    for (int mf = 0; mf < 4; mf++) {
        int rg = row0 + wm + mf * 16 + (lane >> 2);
        #pragma unroll
        for (int nf = 0; nf < 4; nf++) {
            int col = col0 + wn + nf * 8 + (lane & 3) * 2;
            float bx2 = bias ? bias[col] : 0.f;
            float by2 = bias ? bias[col + 1] : 0.f;
            if (rg < M) {
                float2 v = make_float2(acc[mf][nf][0] + bx2, acc[mf][nf][1] + by2);
                *(float2*)(C + (size_t)rg * EMB + col) = v;
            }
            if (rg + 8 < M) {
                float2 v = make_float2(acc[mf][nf][2] + bx2, acc[mf][nf][3] + by2);
                *(float2*)(C + (size_t)(rg + 8) * EMB + col) = v;
            }
        }
    }
}

// fused QKV: blockIdx.z selects weight / bias / destination
__global__ __launch_bounds__(256, 1)
void gemm_qkv(const __nv_bfloat16* __restrict__ Ahi, const __nv_bfloat16* __restrict__ Alo,
              const __nv_bfloat16* __restrict__ Whi, const __nv_bfloat16* __restrict__ Wlo,
              const float* __restrict__ qb, const float* __restrict__ vb,
              float* __restrict__ dq, float* __restrict__ dk, float* __restrict__ dv, int M)
{
    extern __shared__ char smem[];
    const int z = blockIdx.z;
    const size_t woff = (size_t)z * EMB * EMB;
    const float* bias = (z == 0) ? qb : (z == 2) ? vb : nullptr;
    float* C = (z == 0) ? dq : (z == 1) ? dk : dv;
    gemm_body(Ahi, Alo, Whi + woff, Wlo + woff, bias, C, M, smem, blockIdx.x, blockIdx.y);
}

__global__ __launch_bounds__(256, 1)
void gemm_mma(const __nv_bfloat16* __restrict__ Ahi, const __nv_bfloat16* __restrict__ Alo,
              const __nv_bfloat16* __restrict__ Whi, const __nv_bfloat16* __restrict__ Wlo,
              const float* __restrict__ bias, float* __restrict__ C, int M)
{
    extern __shared__ char smem[];
    gemm_body(Ahi, Alo, Whi, Wlo, bias, C, M, smem, blockIdx.x, blockIdx.y);
}

// ---------------- RoPE + split: q,k -> bf16 hi/lo (q pre-scaled into exp2 domain), v -> fp16 hi/lo ----
#define QSCALE 0.18033688011112042f   // 0.125 * log2(e)

__global__ void rope_split(const float* __restrict__ cosb,
                           const float* __restrict__ sinb, int T)
{
    int idx = blockIdx.x * blockDim.x + threadIdx.x;
    int total = T * NH * 32;
    if (idx >= total) return;
    int i = idx & 31;
    int h = (idx >> 5) & 15;
    int t = idx >> 9;
    float c = cosb[t * DH + i];
    float s = sinb[t * DH + i];
    size_t base = (size_t)t * EMB + h * DH;

    float q0 = g_q[base + i], q1 = g_q[base + i + 32];
    float a0 = (q0 * c - q1 * s) * QSCALE;
    float a1 = (q1 * c + q0 * s) * QSCALE;
    __nv_bfloat16 h0 = __float2bfloat16(a0);
    __nv_bfloat16 h1 = __float2bfloat16(a1);
    g_qs_hi[base + i] = h0;
    g_qs_hi[base + i + 32] = h1;
    g_qs_lo[base + i] = __float2bfloat16(a0 - __bfloat162float(h0));
    g_qs_lo[base + i + 32] = __float2bfloat16(a1 - __bfloat162float(h1));

    float k0 = g_k[base + i], k1 = g_k[base + i + 32];
    float b0 = k0 * c - k1 * s;
    float b1 = k1 * c + k0 * s;
    h0 = __float2bfloat16(b0);
    h1 = __float2bfloat16(b1);
    g_ks_hi[base + i] = h0;
    g_ks_hi[base + i + 32] = h1;
    g_ks_lo[base + i] = __float2bfloat16(b0 - __bfloat162float(h0));
    g_ks_lo[base + i + 32] = __float2bfloat16(b1 - __bfloat162float(h1));

    float v0 = g_v[base + i], v1 = g_v[base + i + 32];
    __half hv0 = __float2half_rn(v0);
    __half hv1 = __float2half_rn(v1);
    g_vs_hi[base + i] = hv0;
    g_vs_hi[base + i + 32] = hv1;
    g_vs_lo[base + i] = __float2half_rn(v0 - __half2float(hv0));
    g_vs_lo[base + i + 32] = __float2half_rn(v1 - __half2float(hv1));
}

// ---------------- mma flash attention (exp2-domain, f16x2 MUFU softmax) -----
#define PADS 72
#define QH_OFF 0
#define QL_OFF (128 * PADS)
#define KH_OFF (2 * 128 * PADS)
#define KL_OFF (KH_OFF + 64 * PADS)
#define VH_OFF (KL_OFF + 64 * PADS)
#define VL_OFF (VH_OFF + 64 * PADS)
#define ATT_SMEM ((VL_OFF + 64 * PADS) * 2)
#define MASKV (-30000.f)

__global__ __launch_bounds__(256, 1) void attn_mma(int T)
{
    extern __shared__ char smc[];
    const uint32_t sb = smem_u32(smc);
    const int b = blockIdx.z, h = blockIdx.y, qt = blockIdx.x;
    const int s0 = g_cu[b];
    const int L = g_cu[b + 1] - s0;
    const int q0 = qt * 128;
    if (q0 >= L) return;
    const int tid = threadIdx.x, wid = tid >> 5, lane = tid & 31;

    // ---- load Q (hi+lo) ----
    {
        #pragma unroll
        for (int it = 0; it < 4; it++) {
            int ch = it * 256 + tid;
            int r = ch >> 3, c = ch & 7;
            int gr = min(s0 + q0 + r, T - 1);
            size_t go = (size_t)gr * EMB + h * DH + c * 8;
            uint32_t d = sb + (r * PADS + c * 8) * 2;
            CPA(d + QH_OFF * 2, g_qs_hi + go);
            CPA(d + QL_OFF * 2, g_qs_lo + go);
        }
        CPA_COMMIT();
        asm volatile("cp.async.wait_group 0;" ::: "memory");
        __syncthreads();
    }

    uint32_t qh[4][4], ql[4][4];
    {
        uint32_t qa = sb + ((wid * 16 + (lane & 15)) * PADS) * 2 + (lane >> 4) * 16;
        #pragma unroll
        for (int ks = 0; ks < 4; ks++) {
            LDSM4(qh[ks], qa + QH_OFF * 2 + ks * 32);
            LDSM4(ql[ks], qa + QL_OFF * 2 + ks * 32);
        }
    }

    const int row0 = q0 + wid * 16 + (lane >> 2);
    const int row1 = row0 + 8;
    float m0_ = MASKV, m1_ = MASKV, l0_ = 0.f, l1_ = 0.f;
    float oacc[8][4];
    #pragma unroll
    for (int i = 0; i < 8; i++)
        #pragma unroll
        for (int j = 0; j < 4; j++) oacc[i][j] = 0.f;

    const int nkt = (min(q0 + 128, L) + 63) >> 6;
    const int wrow_max = q0 + wid * 16 + 15;

    const uint32_t kaddr = sb + ((((lane >> 4) << 3) + (lane & 7)) * PADS) * 2 + ((lane >> 3) & 1) * 16;
    const uint32_t vaddr = sb + ((lane & 15) * PADS + ((lane >> 4) << 3)) * 2;

    for (int kt = 0; kt < nkt; kt++) {
        __syncthreads();
        #pragma unroll
        for (int it = 0; it < 2; it++) {
            int ch = it * 256 + tid;
            int r = ch >> 3, c = ch & 7;
            int gr = min(s0 + kt * 64 + r, T - 1);
            size_t go = (size_t)gr * EMB + h * DH + c * 8;
            uint32_t d = sb + (r * PADS + c * 8) * 2;
            CPA(d + KH_OFF * 2, g_ks_hi + go);
            CPA(d + KL_OFF * 2, g_ks_lo + go);
            CPA(d + VH_OFF * 2, g_vs_hi + go);
            CPA(d + VL_OFF * 2, g_vs_lo + go);
        }
        CPA_COMMIT();
        asm volatile("cp.async.wait_group 0;" ::: "memory");
        __syncthreads();

        if (kt * 64 > wrow_max) continue;

        // ---- S = Q K^T (3-product bf16), already in log2 domain ----
        float sacc[8][4];
        #pragma unroll
        for (int i = 0; i < 8; i++)
            #pragma unroll
            for (int j = 0; j < 4; j++) sacc[i][j] = 0.f;

        #pragma unroll
        for (int bp = 0; bp < 4; bp++) {
            #pragma unroll
            for (int ks = 0; ks < 4; ks++) {
                uint32_t kh4[4], kl4[4];
                uint32_t ka = kaddr + (bp * 16 * PADS) * 2 + ks * 32;
                LDSM4(kh4, ka + KH_OFF * 2);
                LDSM4(kl4, ka + KL_OFF * 2);
                MMA(sacc[bp * 2], qh[ks], kh4[0], kh4[1]);
                MMA(sacc[bp * 2], qh[ks], kl4[0], kl4[1]);
                MMA(sacc[bp * 2], ql[ks], kh4[0], kh4[1]);
                MMA(sacc[bp * 2 + 1], qh[ks], kh4[2], kh4[3]);
                MMA(sacc[bp * 2 + 1], qh[ks], kl4[2], kl4[3]);
                MMA(sacc[bp * 2 + 1], ql[ks], kh4[2], kh4[3]);
            }
        }

        // ---- mask + running max ----
        float mx0 = MASKV, mx1 = MASKV;
        #pragma unroll
        for (int nf = 0; nf < 8; nf++) {
            int c0 = kt * 64 + nf * 8 + (lane & 3) * 2;
            int c1 = c0 + 1;
            if (c0 > row0 || c0 >= L) sacc[nf][0] = MASKV;
            if (c1 > row0 || c1 >= L) sacc[nf][1] = MASKV;
            if (c0 > row1 || c0 >= L) sacc[nf][2] = MASKV;
            if (c1 > row1 || c1 >= L) sacc[nf][3] = MASKV;
            mx0 = fmaxf(mx0, fmaxf(sacc[nf][0], sacc[nf][1]));
            mx1 = fmaxf(mx1, fmaxf(sacc[nf][2], sacc[nf][3]));
        }
        mx0 = fmaxf(mx0, __shfl_xor_sync(~0u, mx0, 1));
        mx0 = fmaxf(mx0, __shfl_xor_sync(~0u, mx0, 2));
        mx1 = fmaxf(mx1, __shfl_xor_sync(~0u, mx1, 1));
        mx1 = fmaxf(mx1, __shfl_xor_sync(~0u, mx1, 2));
        float mn0 = fmaxf(m0_, mx0), mn1 = fmaxf(m1_, mx1);
        float corr0 = exp2f(m0_ - mn0), corr1 = exp2f(m1_ - mn1);
        m0_ = mn0; m1_ = mn1;

        #pragma unroll
        for (int nf = 0; nf < 8; nf++) {
            oacc[nf][0] *= corr0; oacc[nf][1] *= corr0;
            oacc[nf][2] *= corr1; oacc[nf][3] *= corr1;
        }

        // ---- P = exp2(S - m) in fp16 (one MUFU per 2 elems), O += P V ----
        float ls0 = 0.f, ls1 = 0.f;
        #pragma unroll
        for (int kk = 0; kk < 4; kk++) {
            uint32_t ph[4];
            ph[0] = ex2h2(sacc[2 * kk][0] - mn0, sacc[2 * kk][1] - mn0);
            ph[1] = ex2h2(sacc[2 * kk][2] - mn1, sacc[2 * kk][3] - mn1);
            ph[2] = ex2h2(sacc[2 * kk + 1][0] - mn0, sacc[2 * kk + 1][1] - mn0);
            ph[3] = ex2h2(sacc[2 * kk + 1][2] - mn1, sacc[2 * kk + 1][3] - mn1);
            float2 f0 = h2f2(ph[0]), f1 = h2f2(ph[1]);
            float2 f2 = h2f2(ph[2]), f3 = h2f2(ph[3]);
            ls0 += f0.x + f0.y + f2.x + f2.y;
            ls1 += f1.x + f1.y + f3.x + f3.y;
            #pragma unroll
            for (int nb = 0; nb < 4; nb++) {
                uint32_t vh4[4], vl4[4];
                uint32_t va = vaddr + (kk * 16 * PADS + nb * 16) * 2;
                LDSM4T(vh4, va + VH_OFF * 2);
                LDSM4T(vl4, va + VL_OFF * 2);
                MMAH(oacc[nb * 2], ph, vh4[0], vh4[1]);
                MMAH(oacc[nb * 2], ph, vl4[0], vl4[1]);
                MMAH(oacc[nb * 2 + 1], ph, vh4[2], vh4[3]);
                MMAH(oacc[nb * 2 + 1], ph, vl4[2], vl4[3]);
            }
        }
        ls0 += __shfl_xor_sync(~0u, ls0, 1);
        ls0 += __shfl_xor_sync(~0u, ls0, 2);
        ls1 += __shfl_xor_sync(~0u, ls1, 1);
        ls1 += __shfl_xor_sync(~0u, ls1, 2);
        l0_ = l0_ * corr0 + ls0;
        l1_ = l1_ * corr1 + ls1;
    }

    // ---- epilogue: normalize, split to bf16 hi/lo ----
    if (row0 < L) {
        float inv = 1.f / l0_;
        #pragma unroll
        for (int nf = 0; nf < 8; nf++) {
            float o0 = oacc[nf][0] * inv, o1 = oacc[nf][1] * inv;
            uint32_t hi = pack_bf2(o0, o1);
            uint32_t lo = pack_bf2_res(o0, o1, hi);
            size_t off = (size_t)(s0 + row0) * EMB + h * DH + nf * 8 + (lane & 3) * 2;
            *(uint32_t*)(g_at_hi + off) = hi;
            *(uint32_t*)(g_at_lo + off) = lo;
        }
    }
    if (row1 < L) {
        float inv = 1.f / l1_;
        #pragma unroll
        for (int nf = 0; nf < 8; nf++) {
            float o0 = oacc[nf][2] * inv, o1 = oacc[nf][3] * inv;
            uint32_t hi = pack_bf2(o0, o1);
            uint32_t lo = pack_bf2_res(o0, o1, hi);
            size_t off = (size_t)(s0 + row1) * EMB + h * DH + nf * 8 + (lane & 3) * 2;
            *(uint32_t*)(g_at_hi + off) = hi;
            *(uint32_t*)(g_at_lo + off) = lo;
        }
    }
}

// ---------------- launch ----------------
extern "C" void kernel_launch(void* const* d_in, const int* in_sizes, int n_in,
                              void* d_out, int out_size)
{
    const float* hidden = (const float*)d_in[0];
    const float* cosb   = (const float*)d_in[1];
    const float* sinb   = (const float*)d_in[2];
    const float* q_w    = (const float*)d_in[3];
    const float* q_b    = (const float*)d_in[4];
    const float* k_w    = (const float*)d_in[5];
    const float* v_w    = (const float*)d_in[6];
    const float* v_b    = (const float*)d_in[7];
    const float* out_w  = (const float*)d_in[8];
    const float* out_b  = (const float*)d_in[9];
    const int*   seqlen = (const int*)d_in[10];
    float* out = (float*)d_out;

    const int T = in_sizes[0] / EMB;
    const int B = in_sizes[10];

    float *dq, *dk, *dv;
    cudaGetSymbolAddress((void**)&dq, g_q);
    cudaGetSymbolAddress((void**)&dk, g_k);
    cudaGetSymbolAddress((void**)&dv, g_v);
    __nv_bfloat16 *hh, *hl, *wh, *wl, *ah, *al;
    cudaGetSymbolAddress((void**)&hh, g_hid_hi);
    cudaGetSymbolAddress((void**)&hl, g_hid_lo);
    cudaGetSymbolAddress((void**)&wh, g_w_hi);
    cudaGetSymbolAddress((void**)&wl, g_w_lo);
    cudaGetSymbolAddress((void**)&ah, g_at_hi);
    cudaGetSymbolAddress((void**)&al, g_at_lo);

    cu_seqlen_kernel<<<1, 32>>>(seqlen, B);

    const int WN4 = EMB * EMB / 4;
    int hn4 = T * EMB / 4;
    cvt_split4<<<(hn4 + 255) / 256, 256>>>(hidden, hh, hl, hn4);
    cvt_split4<<<(WN4 + 255) / 256, 256>>>(q_w,   wh + 0 * (size_t)EMB * EMB, wl + 0 * (size_t)EMB * EMB, WN4);
    cvt_split4<<<(WN4 + 255) / 256, 256>>>(k_w,   wh + 1 * (size_t)EMB * EMB, wl + 1 * (size_t)EMB * EMB, WN4);
    cvt_split4<<<(WN4 + 255) / 256, 256>>>(v_w,   wh + 2 * (size_t)EMB * EMB, wl + 2 * (size_t)EMB * EMB, WN4);
    cvt_split4<<<(WN4 + 255) / 256, 256>>>(out_w, wh + 3 * (size_t)EMB * EMB, wl + 3 * (size_t)EMB * EMB, WN4);

    cudaFuncSetAttribute(gemm_qkv, cudaFuncAttributeMaxDynamicSharedMemorySize, GEMM_SMEM);
    cudaFuncSetAttribute(gemm_mma, cudaFuncAttributeMaxDynamicSharedMemorySize, GEMM_SMEM);
    dim3 gq3(EMB / 128, (T + 127) / 128, 3);
    gemm_qkv<<<gq3, 256, GEMM_SMEM>>>(hh, hl, wh, wl, q_b, v_b, dq, dk, dv, T);

    int rope_total = T * NH * 32;
    rope_split<<<(rope_total + 255) / 256, 256>>>(cosb, sinb, T);

    cudaFuncSetAttribute(attn_mma, cudaFuncAttributeMaxDynamicSharedMemorySize, ATT_SMEM);
    dim3 ga(1024 / 128, NH, B);
    attn_mma<<<ga, 256, ATT_SMEM>>>(T);

    dim3 gg(EMB / 128, (T + 127) / 128);
    gemm_mma<<<gg, 256, GEMM_SMEM>>>(ah, al, wh + 3 * (size_t)EMB * EMB, wl + 3 * (size_t)EMB * EMB, out_b, out, T);
}